// round 14
// baseline (speedup 1.0000x reference)
#include <cuda_runtime.h>
#include <cuda_bf16.h>
#include <math.h>

// Problem constants (fixed by reference setup_inputs)
#define N_TOK   4096        // B*S = 2*2048
#define DIM     1024
#define NEXP    8
#define CAP     1280        // floor(2*1.25*4096/8), even
#define ECAP    (NEXP*CAP)  // 10240
#define TPB     16          // tokens per block in phase A
#define NCHUNK  (N_TOK/TPB) // 256 blocks in phase A
#define NASSIGN (2*N_TOK)   // 8192

// Output layout (floats), concatenated in reference return order:
//  W  : [N, E, CAP],  M : [N, E, CAP],  Bt : [E, CAP, DIM],  L : [N, E]
#define OFF_W  ((size_t)0)
#define OFF_M  ((size_t)N_TOK * NEXP * CAP)     // 41,943,040 floats
#define OFF_B  (OFF_M + (size_t)N_TOK * NEXP * CAP)
#define OFF_L  (OFF_B + (size_t)NEXP * CAP * DIM)

// Fill geometry: W+M = 83,886,080 floats = 2560 spans of 32768 floats (128 KB)
#define SPAN_FLOATS 32768
#define N_SPANS     2560      // spans 0-1279 = W, 1280-2559 = M (OFF_M/32768 = 1280 exactly)
#define M_SPAN_OFS  1280
#define BUCKET_CAP  16        // max patches per span is 10 by construction
#define BT_PER_BLOCK 4
#define FILL_BLOCKS (N_SPANS + ECAP / BT_PER_BLOCK)   // 2560 + 2560 = 5120

// Scratch (__device__ globals; no allocation allowed; zero-initialized at load)
__device__ unsigned g_done = 0;               // last-block counter (self-resetting)
__device__ int   g_slot_token[ECAP];          // slot -> token, -1 = empty
__device__ int   g_cnt [NCHUNK][2][NEXP];     // per-chunk per-k per-expert counts
__device__ int   g_meta[2][N_TOK];            // e | (in_chunk_rank << 8)
__device__ float g_prob[2][N_TOK];            // gating prob per (k, token)
__device__ int   g_bucket_cnt[N_SPANS];                // patches per span
__device__ int   g_bucket_idx[N_SPANS * BUCKET_CAP];   // local float index in span
__device__ float g_bucket_val[N_SPANS * BUCKET_CAP];   // value to write

// ---------------------------------------------------------------------------
// kA: fused logits + top-2 gating + per-chunk counts/ranks; the LAST block to
// finish additionally runs the global routing (prefix scan + slot scatter +
// patch bucketing). grid = 256, block = 256; 2 tokens/warp, MLP=16 x-loads.
// ---------------------------------------------------------------------------
__global__ void kA_gate(const float4* __restrict__ X4,
                        const float4* __restrict__ G4,
                        float* __restrict__ L)
{
    __shared__ int s_sel[2][TPB];
    __shared__ int s_last;
    __shared__ int s_base[NCHUNK][2][NEXP];   // 16 KB, used only by last block

    const int warp = threadIdx.x >> 5;
    const int lane = threadIdx.x & 31;
    const int n0 = blockIdx.x * TPB + warp * 2;    // first of two tokens

    // front-batch: 16 outstanding LDG.128 per thread
    float4 xv0[8], xv1[8];
#pragma unroll
    for (int i = 0; i < 8; ++i)
        xv0[i] = X4[(size_t)n0 * 256 + 32 * i + lane];
#pragma unroll
    for (int i = 0; i < 8; ++i)
        xv1[i] = X4[(size_t)(n0 + 1) * 256 + 32 * i + lane];

    float acc0[NEXP], acc1[NEXP];
#pragma unroll
    for (int e = 0; e < NEXP; ++e) {
        float a0 = 0.f, a1 = 0.f;
#pragma unroll
        for (int i = 0; i < 8; ++i) {
            const float4 wv = G4[e * 256 + 32 * i + lane];
            a0 += xv0[i].x * wv.x + xv0[i].y * wv.y + xv0[i].z * wv.z + xv0[i].w * wv.w;
            a1 += xv1[i].x * wv.x + xv1[i].y * wv.y + xv1[i].z * wv.z + xv1[i].w * wv.w;
        }
        acc0[e] = a0;
        acc1[e] = a1;
    }
#pragma unroll
    for (int e = 0; e < NEXP; ++e) {
#pragma unroll
        for (int s = 16; s > 0; s >>= 1) {
            acc0[e] += __shfl_xor_sync(0xffffffffu, acc0[e], s);
            acc1[e] += __shfl_xor_sync(0xffffffffu, acc1[e], s);
        }
    }

    if (lane == 0) {
#pragma unroll
        for (int t = 0; t < 2; ++t) {
            const int n = n0 + t;
            const float* acc = t ? acc1 : acc0;
            ((float4*)L)[(size_t)n * 2 + 0] = make_float4(acc[0], acc[1], acc[2], acc[3]);
            ((float4*)L)[(size_t)n * 2 + 1] = make_float4(acc[4], acc[5], acc[6], acc[7]);

            int i1 = 0; float v1 = acc[0];
#pragma unroll
            for (int e = 1; e < NEXP; ++e) if (acc[e] > v1) { v1 = acc[e]; i1 = e; }
            int i2 = -1; float v2 = -INFINITY;
#pragma unroll
            for (int e = 0; e < NEXP; ++e)
                if (e != i1 && acc[e] > v2) { v2 = acc[e]; i2 = e; }

            const float mx = fmaxf(v1, v2);
            const float e1 = expf(v1 - mx), e2 = expf(v2 - mx);
            const float inv = 1.f / (e1 + e2);
            g_prob[0][n] = e1 * inv;
            g_prob[1][n] = e2 * inv;
            s_sel[0][warp * 2 + t] = i1;
            s_sel[1][warp * 2 + t] = i2;
        }
    }
    __syncthreads();

    if (threadIdx.x < 2 * TPB) {          // in-chunk ranks (32 assignments)
        const int k = threadIdx.x >> 4;
        const int t = threadIdx.x & (TPB - 1);
        const int e = s_sel[k][t];
        int r = 0;
#pragma unroll
        for (int w = 0; w < TPB; ++w) r += (w < t) && (s_sel[k][w] == e);
        g_meta[k][blockIdx.x * TPB + t] = e | (r << 8);
    }
    if (threadIdx.x >= 64 && threadIdx.x < 80) {   // per-chunk counts (16 pairs)
        const int idx = threadIdx.x - 64;
        const int k = idx >> 3;
        const int e = idx & 7;
        int c = 0;
#pragma unroll
        for (int w = 0; w < TPB; ++w) c += (s_sel[k][w] == e);
        g_cnt[blockIdx.x][k][e] = c;
    }
    __syncthreads();

    // ---- last-block handshake ----
    if (threadIdx.x == 0) {
        __threadfence();                       // publish this block's writes
        const unsigned old = atomicAdd(&g_done, 1u);
        s_last = (old == gridDim.x - 1) ? 1 : 0;
    }
    __syncthreads();
    if (!s_last) return;
    __threadfence();                           // observe all blocks' writes

    // ---- routing (runs in the single last block) ----
    const int tid  = threadIdx.x;
    const int e    = tid >> 5;                 // expert (8 warps)
    const int ln   = tid & 31;

    for (int i = tid; i < ECAP; i += 256)    g_slot_token[i] = -1;
    for (int i = tid; i < N_SPANS; i += 256) g_bucket_cnt[i] = 0;
    __syncthreads();

    // exclusive k-major prefix over chunk counts (warp e owns expert e)
    int carry = 0;
    for (int k = 0; k < 2; ++k) {
        for (int c0 = 0; c0 < NCHUNK; c0 += 32) {
            const int v = g_cnt[c0 + ln][k][e];
            int inc = v;
#pragma unroll
            for (int s = 1; s < 32; s <<= 1) {
                const int t = __shfl_up_sync(0xffffffffu, inc, s);
                if (ln >= s) inc += t;
            }
            s_base[c0 + ln][k][e] = carry + (inc - v);
            carry += __shfl_sync(0xffffffffu, inc, 31);
        }
    }
    __syncthreads();

    // scatter: slot map + per-span patch buckets (8192 assignments)
#pragma unroll 4
    for (int idx = tid; idx < NASSIGN; idx += 256) {
        const int k = idx >> 12;
        const int n = idx & (N_TOK - 1);
        const int meta = g_meta[k][n];
        const int ee = meta & 255;
        const int r  = meta >> 8;
        const int rank = s_base[n / TPB][k][ee] + r;
        if (rank < CAP) {
            const int woff = n * ECAP + ee * CAP + rank;   // < 2^26
            g_slot_token[ee * CAP + rank] = n;

            const int sp = woff >> 15;                     // /32768
            const int li = woff & (SPAN_FLOATS - 1);
            const int pW = atomicAdd(&g_bucket_cnt[sp], 1);
            g_bucket_idx[sp * BUCKET_CAP + pW] = li;
            g_bucket_val[sp * BUCKET_CAP + pW] = g_prob[k][n];

            const int spM = sp + M_SPAN_OFS;               // same local index in M
            const int pM = atomicAdd(&g_bucket_cnt[spM], 1);
            g_bucket_idx[spM * BUCKET_CAP + pM] = li;
            g_bucket_val[spM * BUCKET_CAP + pM] = 1.0f;
        }
    }
    __syncthreads();
    if (tid == 0) g_done = 0;                  // reset for next graph replay
}

// ---------------------------------------------------------------------------
// kFill: one uniform pass writing the entire W+M+Bt output.
//  blocks [0, 2560):      zero a 128 KB span with streaming stores, then apply
//                         that span's sparse patches (ordered by __syncthreads)
//  blocks [2560, 5120):   fill 4 expert-batch slots (token row or zeros)
// ---------------------------------------------------------------------------
__global__ void kFill(const float4* __restrict__ X4,
                      float4* __restrict__ out4)
{
    const int tid = threadIdx.x;
    const int bid = blockIdx.x;
    const float4 z = make_float4(0.f, 0.f, 0.f, 0.f);

    if (bid < N_SPANS) {
        float4* __restrict__ P = out4 + (size_t)bid * (SPAN_FLOATS / 4);
#pragma unroll
        for (int i = 0; i < SPAN_FLOATS / 4 / 256; ++i)    // 32 stcs.128
            __stcs(P + tid + 256 * i, z);
        __syncthreads();                                    // order zero -> patch
        const int cnt = g_bucket_cnt[bid];
        if (tid < cnt) {
            ((float*)P)[g_bucket_idx[bid * BUCKET_CAP + tid]] =
                g_bucket_val[bid * BUCKET_CAP + tid];
        }
    } else {
        float4* __restrict__ B4 = out4 + (OFF_B / 4);
        const int slot0 = (bid - N_SPANS) * BT_PER_BLOCK;
#pragma unroll
        for (int j = 0; j < BT_PER_BLOCK; ++j) {
            const int slot = slot0 + j;                     // e*CAP + c
            const int t = g_slot_token[slot];               // broadcast load
            float4 o;
            if (t >= 0) o = X4[(size_t)t * 256 + tid];
            else        o = z;
            __stcs(B4 + (size_t)slot * 256 + tid, o);
        }
    }
}

// ---------------------------------------------------------------------------
extern "C" void kernel_launch(void* const* d_in, const int* in_sizes, int n_in,
                              void* d_out, int out_size)
{
    const float* x      = (const float*)d_in[0];   // [2,2048,1024]
    const float* w_gate = (const float*)d_in[1];   // [8,1024]
    float* out = (float*)d_out;
    float* L  = out + OFF_L;

    // Two kernels, one stream, no events: gate+route, then fill+patch.
    kA_gate<<<NCHUNK, 256>>>((const float4*)x, (const float4*)w_gate, L);
    kFill<<<FILL_BLOCKS, 256>>>((const float4*)x, (float4*)out);
}

// round 15
// speedup vs baseline: 1.1609x; 1.1609x over previous
#include <cuda_runtime.h>
#include <cuda_bf16.h>
#include <math.h>

// Problem constants (fixed by reference setup_inputs)
#define N_TOK   4096        // B*S = 2*2048
#define DIM     1024
#define NEXP    8
#define CAP     1280        // floor(2*1.25*4096/8), even
#define ECAP    (NEXP*CAP)  // 10240
#define TPB     16          // tokens per block in phase A
#define NCHUNK  (N_TOK/TPB) // 256 blocks in phase A
#define NASSIGN (2*N_TOK)   // 8192

// Output layout (floats), concatenated in reference return order:
//  W  : [N, E, CAP],  M : [N, E, CAP],  Bt : [E, CAP, DIM],  L : [N, E]
#define OFF_W  ((size_t)0)
#define OFF_M  ((size_t)N_TOK * NEXP * CAP)     // 41,943,040 floats
#define OFF_B  (OFF_M + (size_t)N_TOK * NEXP * CAP)
#define OFF_L  (OFF_B + (size_t)NEXP * CAP * DIM)

// Fill geometry: W+M = 83,886,080 floats = 2560 spans of 32768 floats (128 KB)
#define SPAN_FLOATS 32768
#define N_SPANS     2560      // spans 0-1279 = W, 1280-2559 = M (OFF_M/32768 = 1280)
#define M_SPAN_OFS  1280
#define BUCKET_CAP  16        // max patches per span ~8 by construction
#define BT_PER_BLOCK 4
#define FILL_BLOCKS (N_SPANS + ECAP / BT_PER_BLOCK)   // 2560 + 2560 = 5120

// Scratch (__device__ globals; no allocation allowed)
__device__ int   g_slot_token[ECAP];          // slot -> token, -1 = empty
__device__ int   g_cnt [NCHUNK][2][NEXP];     // per-chunk per-k per-expert counts
__device__ int   g_meta[2][N_TOK];            // e | (in_chunk_rank << 8)
__device__ float g_prob[2][N_TOK];            // gating prob per (k, token)
__device__ int   g_bucket_cnt[N_SPANS];                // patches per span
__device__ int   g_bucket_idx[N_SPANS * BUCKET_CAP];   // local float index in span
__device__ float g_bucket_val[N_SPANS * BUCKET_CAP];   // value to write

// ---------------------------------------------------------------------------
// kA: fused logits + top-2 gating + per-chunk counts / in-chunk ranks.
// grid = 256, block = 256 (8 warps); 2 tokens/warp, MLP=16 front-batched
// x-loads; w_gate float4s L1-resident and reused. (Measured ~7 us in R13.)
// ---------------------------------------------------------------------------
__global__ void kA_gate(const float4* __restrict__ X4,
                        const float4* __restrict__ G4,
                        float* __restrict__ L)
{
    __shared__ int s_sel[2][TPB];

    const int warp = threadIdx.x >> 5;
    const int lane = threadIdx.x & 31;
    const int n0 = blockIdx.x * TPB + warp * 2;    // first of two tokens

    float4 xv0[8], xv1[8];
#pragma unroll
    for (int i = 0; i < 8; ++i)
        xv0[i] = X4[(size_t)n0 * 256 + 32 * i + lane];
#pragma unroll
    for (int i = 0; i < 8; ++i)
        xv1[i] = X4[(size_t)(n0 + 1) * 256 + 32 * i + lane];

    float acc0[NEXP], acc1[NEXP];
#pragma unroll
    for (int e = 0; e < NEXP; ++e) {
        float a0 = 0.f, a1 = 0.f;
#pragma unroll
        for (int i = 0; i < 8; ++i) {
            const float4 wv = G4[e * 256 + 32 * i + lane];
            a0 += xv0[i].x * wv.x + xv0[i].y * wv.y + xv0[i].z * wv.z + xv0[i].w * wv.w;
            a1 += xv1[i].x * wv.x + xv1[i].y * wv.y + xv1[i].z * wv.z + xv1[i].w * wv.w;
        }
        acc0[e] = a0;
        acc1[e] = a1;
    }
#pragma unroll
    for (int e = 0; e < NEXP; ++e) {
#pragma unroll
        for (int s = 16; s > 0; s >>= 1) {
            acc0[e] += __shfl_xor_sync(0xffffffffu, acc0[e], s);
            acc1[e] += __shfl_xor_sync(0xffffffffu, acc1[e], s);
        }
    }

    if (lane == 0) {
#pragma unroll
        for (int t = 0; t < 2; ++t) {
            const int n = n0 + t;
            const float* acc = t ? acc1 : acc0;
            ((float4*)L)[(size_t)n * 2 + 0] = make_float4(acc[0], acc[1], acc[2], acc[3]);
            ((float4*)L)[(size_t)n * 2 + 1] = make_float4(acc[4], acc[5], acc[6], acc[7]);

            int i1 = 0; float v1 = acc[0];
#pragma unroll
            for (int e = 1; e < NEXP; ++e) if (acc[e] > v1) { v1 = acc[e]; i1 = e; }
            int i2 = -1; float v2 = -INFINITY;
#pragma unroll
            for (int e = 0; e < NEXP; ++e)
                if (e != i1 && acc[e] > v2) { v2 = acc[e]; i2 = e; }

            const float mx = fmaxf(v1, v2);
            const float e1 = expf(v1 - mx), e2 = expf(v2 - mx);
            const float inv = 1.f / (e1 + e2);
            g_prob[0][n] = e1 * inv;
            g_prob[1][n] = e2 * inv;
            s_sel[0][warp * 2 + t] = i1;
            s_sel[1][warp * 2 + t] = i2;
        }
    }
    __syncthreads();

    if (threadIdx.x < 2 * TPB) {          // in-chunk ranks (32 assignments)
        const int k = threadIdx.x >> 4;
        const int t = threadIdx.x & (TPB - 1);
        const int e = s_sel[k][t];
        int r = 0;
#pragma unroll
        for (int w = 0; w < TPB; ++w) r += (w < t) && (s_sel[k][w] == e);
        g_meta[k][blockIdx.x * TPB + t] = e | (r << 8);
    }
    if (threadIdx.x >= 64 && threadIdx.x < 80) {   // per-chunk counts (16 pairs)
        const int idx = threadIdx.x - 64;
        const int k = idx >> 3;
        const int e = idx & 7;
        int c = 0;
#pragma unroll
        for (int w = 0; w < TPB; ++w) c += (s_sel[k][w] == e);
        g_cnt[blockIdx.x][k][e] = c;
    }
}

// ---------------------------------------------------------------------------
// kRoute (1 block, 256 thr): slot init + k-major prefix scan + slot scatter
// + per-span patch buckets for kFill.
// ---------------------------------------------------------------------------
__global__ void kRoute()
{
    __shared__ int s_base[NCHUNK][2][NEXP];   // 16 KB: per-chunk exclusive bases
    __shared__ int s_bcnt[N_SPANS];           // 10 KB: bucket counters in smem

    const int tid  = threadIdx.x;
    const int e    = tid >> 5;           // expert (8 warps)
    const int lane = tid & 31;

    for (int i = tid; i < ECAP; i += 256)    g_slot_token[i] = -1;
    for (int i = tid; i < N_SPANS; i += 256) s_bcnt[i] = 0;

    // exclusive k-major prefix over chunk counts (warp e owns expert e)
    int carry = 0;
    for (int k = 0; k < 2; ++k) {
        for (int c0 = 0; c0 < NCHUNK; c0 += 32) {
            const int v = g_cnt[c0 + lane][k][e];
            int inc = v;
#pragma unroll
            for (int s = 1; s < 32; s <<= 1) {
                const int t = __shfl_up_sync(0xffffffffu, inc, s);
                if (lane >= s) inc += t;
            }
            s_base[c0 + lane][k][e] = carry + (inc - v);
            carry += __shfl_sync(0xffffffffu, inc, 31);
        }
    }
    __syncthreads();

    // scatter: slot map + per-span patch buckets (8192 assignments)
#pragma unroll 4
    for (int idx = tid; idx < NASSIGN; idx += 256) {
        const int k = idx >> 12;
        const int n = idx & (N_TOK - 1);
        const int meta = g_meta[k][n];
        const int ee = meta & 255;
        const int r  = meta >> 8;
        const int rank = s_base[n / TPB][k][ee] + r;
        if (rank < CAP) {
            const int woff = n * ECAP + ee * CAP + rank;   // < 2^26
            g_slot_token[ee * CAP + rank] = n;

            const int sp = woff >> 15;                     // /32768
            const int li = woff & (SPAN_FLOATS - 1);
            const int pW = atomicAdd(&s_bcnt[sp], 1);
            g_bucket_idx[sp * BUCKET_CAP + pW] = li;
            g_bucket_val[sp * BUCKET_CAP + pW] = g_prob[k][n];

            const int spM = sp + M_SPAN_OFS;               // same local index in M
            const int pM = atomicAdd(&s_bcnt[spM], 1);
            g_bucket_idx[spM * BUCKET_CAP + pM] = li;
            g_bucket_val[spM * BUCKET_CAP + pM] = 1.0f;
        }
    }
    __syncthreads();

    for (int i = tid; i < N_SPANS; i += 256) g_bucket_cnt[i] = s_bcnt[i];
}

// ---------------------------------------------------------------------------
// kFill: one uniform pass writing the entire W+M+Bt output (measured
// 56.8 us @ 5.94 TB/s in R14 — unchanged).
//  blocks [0, 2560):      zero a 128 KB span (32 stcs.128/thread), then apply
//                         that span's sparse patches (ordered by __syncthreads)
//  blocks [2560, 5120):   fill 4 expert-batch slots (token row or zeros)
// ---------------------------------------------------------------------------
__global__ void kFill(const float4* __restrict__ X4,
                      float4* __restrict__ out4)
{
    const int tid = threadIdx.x;
    const int bid = blockIdx.x;
    const float4 z = make_float4(0.f, 0.f, 0.f, 0.f);

    if (bid < N_SPANS) {
        float4* __restrict__ P = out4 + (size_t)bid * (SPAN_FLOATS / 4);
#pragma unroll
        for (int i = 0; i < SPAN_FLOATS / 4 / 256; ++i)    // 32 stcs.128
            __stcs(P + tid + 256 * i, z);
        __syncthreads();                                    // order zero -> patch
        const int cnt = g_bucket_cnt[bid];
        if (tid < cnt) {
            ((float*)P)[g_bucket_idx[bid * BUCKET_CAP + tid]] =
                g_bucket_val[bid * BUCKET_CAP + tid];
        }
    } else {
        float4* __restrict__ B4 = out4 + (OFF_B / 4);
        const int slot0 = (bid - N_SPANS) * BT_PER_BLOCK;
#pragma unroll
        for (int j = 0; j < BT_PER_BLOCK; ++j) {
            const int slot = slot0 + j;                     // e*CAP + c
            const int t = g_slot_token[slot];               // broadcast load
            float4 o;
            if (t >= 0) o = X4[(size_t)t * 256 + tid];
            else        o = z;
            __stcs(B4 + (size_t)slot * 256 + tid, o);
        }
    }
}

// ---------------------------------------------------------------------------
extern "C" void kernel_launch(void* const* d_in, const int* in_sizes, int n_in,
                              void* d_out, int out_size)
{
    const float* x      = (const float*)d_in[0];   // [2,2048,1024]
    const float* w_gate = (const float*)d_in[1];   // [8,1024]
    float* out = (float*)d_out;
    float* L  = out + OFF_L;

    // Three kernels, one stream, no events.
    kA_gate<<<NCHUNK, 256>>>((const float4*)x, (const float4*)w_gate, L);
    kRoute<<<1, 256>>>();
    kFill<<<FILL_BLOCKS, 256>>>((const float4*)x, (float4*)out);
}